// round 16
// baseline (speedup 1.0000x reference)
#include <cuda_runtime.h>
#include <cstdint>

#define OC 64
#define IC 208
#define EPSV 1e-5f
#define PD 38
#define PH 38
#define PW 40
#define PCH (PD * PH * PW)
#define KTAPS 352
#define NK16 22                       // k16 chunks per channel
#define CHUNK_U4 256                  // uint4 per chunk (8 nblk * 32 lanes)
#define BCH_U4 (NK16 * CHUNK_U4)      // 5632 uint4 per channel

__device__ float g_P[(size_t)4 * IC * PCH];
__device__ uint4 g_W[(size_t)IC * BCH_U4 + CHUNK_U4];   // +1 chunk tail pad for prefetch
__device__ float g_ss[OC];
__device__ float g_scale[OC];

// ---------------- helpers ----------------
static __device__ __forceinline__ uint32_t to_tf32(float x) {
    uint32_t r; asm("cvt.rn.tf32.f32 %0, %1;" : "=r"(r) : "f"(x));
    return r;
}
static __device__ __forceinline__ void mma_tf32(float* d, const uint32_t* a,
                                                uint32_t b0, uint32_t b1) {
    asm volatile("mma.sync.aligned.m16n8k8.row.col.f32.tf32.tf32.f32 "
        "{%0,%1,%2,%3}, {%4,%5,%6,%7}, {%8,%9}, {%0,%1,%2,%3};"
        : "+f"(d[0]), "+f"(d[1]), "+f"(d[2]), "+f"(d[3])
        : "r"(a[0]), "r"(a[1]), "r"(a[2]), "r"(a[3]), "r"(b0), "r"(b1));
}

#define CPA(dst, src) asm volatile("cp.async.cg.shared.global [%0], [%1], 16;" :: "r"(dst), "l"(src))
#define CPC() asm volatile("cp.async.commit_group;" ::)
#define CPW1() asm volatile("cp.async.wait_group 1;" ::: "memory")
#define CPW0() asm volatile("cp.async.wait_group 0;" ::: "memory")

// ---------------- K1: build weights into tf32 mma B-fragment layout ----------------
__global__ void build_w_kernel(
    int c0, int c1,
    const float* __restrict__ wss, const float* __restrict__ wsv, const float* __restrict__ wst,
    const float* __restrict__ wvs, const float* __restrict__ wvv, const float* __restrict__ wvt,
    const float* __restrict__ bss, const float* __restrict__ bsv, const float* __restrict__ bst,
    const float* __restrict__ bvs, const float* __restrict__ bvv, const float* __restrict__ bvt) {
    int idx = blockIdx.x * blockDim.x + threadIdx.x;
    int n = (c1 - c0) * KTAPS * 64;
    if (idx >= n) return;
    int oc  = idx & 63;
    int tap = (idx >> 6) % KTAPS;
    int c   = c0 + idx / (KTAPS * 64);

    float val = 0.f;
    if (tap < 343) {
        int u, io, dout;
        if (oc < 16) { u = oc; io = 0; dout = 1; }
        else         { u = (oc - 16) / 3; io = (oc - 16) % 3; dout = 3; }
        int v, ji, din;
        if (c < 16)       { v = c;            ji = 0;            din = 1; }
        else if (c < 64)  { v = (c - 16) / 3; ji = (c - 16) % 3; din = 3; }
        else              { v = (c - 64) / 9; ji = (c - 64) % 9; din = 9; }
        const float* w; const float* bs; int nb;
        if (oc < 16) {
            if (c < 16)      { w = wss; bs = bss; nb = 3; }
            else if (c < 64) { w = wsv; bs = bsv; nb = 3; }
            else             { w = wst; bs = bst; nb = 9; }
        } else {
            if (c < 16)      { w = wvs; bs = bvs; nb = 3; }
            else if (c < 64) { w = wvv; bs = bvv; nb = 9; }
            else             { w = wvt; bs = bvt; nb = 21; }
        }
        for (int bb = 0; bb < nb; bb++)
            val = fmaf(w[(u * 16 + v) * nb + bb],
                       bs[((bb * dout + io) * din + ji) * 343 + tap], val);
    }
    // B fragment (m16n8k8 row.col): lane = (oc%8)*4 + (kk%4); word = kk/4
    int q = tap >> 4, kk = tap & 15;
    int j = oc >> 3;
    int lane = ((oc & 7) << 2) + (kk & 3);
    size_t u4 = ((size_t)c * NK16 + q) * CHUNK_U4 + j * 32 + lane;
    ((uint32_t*)&g_W[u4])[kk >> 2] = to_tf32(val);
}

// ---------------- K2: padded svt ----------------
__global__ void pad_kernel(const float* __restrict__ sv) {
    long long idx = (long long)blockIdx.x * 256 + threadIdx.x;
    if (idx >= (long long)4 * IC * PCH) return;
    int bc = (int)(idx / PCH);
    int r  = (int)(idx - (long long)bc * PCH);
    int b = bc / IC, c = bc % IC;
    int pd = r / (PH * PW); r -= pd * (PH * PW);
    int ph = r / PW;
    int pw = r - ph * PW;
    int id = pd - 3, ih = ph - 3, iw = pw - 3;
    float val = 0.f;
    if ((unsigned)id < 32u && (unsigned)ih < 32u && (unsigned)iw < 32u) {
        int off = id * 1024 + ih * 32 + iw;
        const float* svb = sv + (size_t)b * 64 * 32768;
        if (c < 64) val = svb[(size_t)c * 32768 + off];
        else {
            int cc = c - 64, u = cc / 9, comp = cc % 9;
            val = svb[(size_t)(16 + u * 3 + comp / 3) * 32768 + off] *
                  svb[(size_t)(16 + u * 3 + comp % 3) * 32768 + off];
        }
    }
    g_P[idx] = val;
}

// ---------------- K3: mma.sync tf32, B direct from L2 via LDG.128 ----------------
// 256 thr = 8 warps; warp w: 16 voxels (rows m0=w*16+lane/4, m1=m0+8) x 64 oc.
extern __shared__ float smem[];

__global__ void __launch_bounds__(256, 1)
conv_kernel(float* __restrict__ out) {
    int*   tapoff = (int*)smem;
    float* s_in   = smem + 352;

    const int tid = threadIdx.x, lane = tid & 31, w = tid >> 5;
    const int tile = blockIdx.x, b = blockIdx.y;
    const int td = (tile >> 2) * 2, th = ((tile >> 1) & 1) * 8, tw = (tile & 1) * 8;

    for (int t = tid; t < KTAPS; t += 256) {
        int kd = t / 49, r = t % 49, kh = r / 7, kw = r % 7;
        tapoff[t] = (t < 343) ? (kd * 504 + kh * 24 + kw) : 0;
    }

    const int c4 = lane & 3;
    const int m0 = w * 16 + (lane >> 2), m1 = m0 + 8;
    const int g0 = (m0 >> 6) * 1008 + ((m0 >> 3) & 7) * 48 + (m0 & 7) * 2;
    const int g1 = (m1 >> 6) * 1008 + ((m1 >> 3) & 7) * 48 + (m1 & 7) * 2;

    const uint32_t inb = (uint32_t)__cvta_generic_to_shared(s_in);

    auto stage = [&](int c) {
        int buf = c & 1;
        const float* src = g_P + ((size_t)b * IC + c) * PCH
                         + (2 * td) * (PH * PW) + (2 * th) * PW + (2 * tw);
        uint32_t dsti = inb + (uint32_t)buf * 4536 * 4;
        for (int i = tid; i < 189 * 6; i += 256) {
            int dd = i / 126, r2 = i - dd * 126, dh = r2 / 6, ch = r2 - dh * 6;
            CPA(dsti + ((dd * 21 + dh) * 24 + ch * 4) * 4,
                src + dd * (PH * PW) + dh * PW + ch * 4);
        }
    };

    float acc[8][4];
#pragma unroll
    for (int j = 0; j < 8; j++)
#pragma unroll
        for (int k = 0; k < 4; k++) acc[j][k] = 0.f;

    stage(0); CPC();
    stage(1); CPC();

    // Flat B pointer: chunks contiguous across [c][q]. Prefetch chunk 0.
    const uint4* __restrict__ pB = g_W + lane;
    uint4 b0[8], b1[8];
#pragma unroll
    for (int j = 0; j < 8; j++) b0[j] = pB[j * 32];
    pB += CHUNK_U4;

    for (int c = 0; c < IC; c++) {
        if (c < IC - 1) CPW1(); else CPW0();
        __syncthreads();

        const float* si = s_in + (c & 1) * 4536;

#pragma unroll 1
        for (int qq = 0; qq < 11; qq++) {
            const int q = 2 * qq;
            // prefetch chunk q+1 into b1 (overlaps with chunk q's gather+mma)
#pragma unroll
            for (int j = 0; j < 8; j++) b1[j] = pB[j * 32];
            pB += CHUNK_U4;

            {   // compute chunk q with b0
                const int* tq = tapoff + q * 16 + c4;
                int o0 = tq[0], o1 = tq[4], o2 = tq[8], o3 = tq[12];
                uint32_t a1[4], a2[4];
                a1[0] = to_tf32(si[g0 + o0]); a1[1] = to_tf32(si[g1 + o0]);
                a1[2] = to_tf32(si[g0 + o1]); a1[3] = to_tf32(si[g1 + o1]);
                a2[0] = to_tf32(si[g0 + o2]); a2[1] = to_tf32(si[g1 + o2]);
                a2[2] = to_tf32(si[g0 + o3]); a2[3] = to_tf32(si[g1 + o3]);
#pragma unroll
                for (int j = 0; j < 8; j++) {
                    mma_tf32(acc[j], a1, b0[j].x, b0[j].y);
                    mma_tf32(acc[j], a2, b0[j].z, b0[j].w);
                }
            }

            // prefetch chunk q+2 (or next channel's chunk 0 / tail pad) into b0
#pragma unroll
            for (int j = 0; j < 8; j++) b0[j] = pB[j * 32];
            pB += CHUNK_U4;

            {   // compute chunk q+1 with b1
                const int* tq = tapoff + (q + 1) * 16 + c4;
                int o0 = tq[0], o1 = tq[4], o2 = tq[8], o3 = tq[12];
                uint32_t a1[4], a2[4];
                a1[0] = to_tf32(si[g0 + o0]); a1[1] = to_tf32(si[g1 + o0]);
                a1[2] = to_tf32(si[g0 + o1]); a1[3] = to_tf32(si[g1 + o1]);
                a2[0] = to_tf32(si[g0 + o2]); a2[1] = to_tf32(si[g1 + o2]);
                a2[2] = to_tf32(si[g0 + o3]); a2[3] = to_tf32(si[g1 + o3]);
#pragma unroll
                for (int j = 0; j < 8; j++) {
                    mma_tf32(acc[j], a1, b1[j].x, b1[j].y);
                    mma_tf32(acc[j], a2, b1[j].z, b1[j].w);
                }
            }
        }
        // pB now points at chunk 1 of channel c+1 (b0 holds its chunk 0);
        // for the last channel, b0 holds the tail pad (never consumed).

        if (c + 2 < IC) {
            __syncthreads();
            stage(c + 2); CPC();
        }
    }

    // epilogue: D frag (row lane/4 [+8], col j*8 + 2*c4 [+1])
    const int od0 = td + (m0 >> 6), oh0 = th + ((m0 >> 3) & 7), ow0 = tw + (m0 & 7);
    const int od1 = td + (m1 >> 6), oh1 = th + ((m1 >> 3) & 7), ow1 = tw + (m1 & 7);
    float* ob = out + (size_t)b * OC * 4096;
    const int v0 = od0 * 256 + oh0 * 16 + ow0;
    const int v1 = od1 * 256 + oh1 * 16 + ow1;
#pragma unroll
    for (int j = 0; j < 8; j++) {
        int oc0 = j * 8 + 2 * c4;
        ob[(size_t)oc0 * 4096 + v0]       = acc[j][0];
        ob[(size_t)(oc0 + 1) * 4096 + v0] = acc[j][1];
        ob[(size_t)oc0 * 4096 + v1]       = acc[j][2];
        ob[(size_t)(oc0 + 1) * 4096 + v1] = acc[j][3];
    }
}

// ---------------- epilogue kernels ----------------
__global__ void sumsq_kernel(const float* __restrict__ y) {
    __shared__ float red[256];
    const int ch = blockIdx.x, tid = threadIdx.x;
    float s = 0.f;
    for (int i = tid; i < 4 * 4096; i += 256) {
        int b = i >> 12, sp = i & 4095;
        float v = y[((size_t)b * OC + ch) * 4096 + sp];
        s = fmaf(v, v, s);
    }
    red[tid] = s;
    __syncthreads();
    for (int o = 128; o > 0; o >>= 1) {
        if (tid < o) red[tid] += red[tid + o];
        __syncthreads();
    }
    if (tid == 0) g_ss[ch] = red[0];
}

__global__ void finalize_kernel(const float* __restrict__ bngs, const float* __restrict__ bngv) {
    int ch = threadIdx.x;
    float sc;
    if (ch < 16) sc = bngs[ch] / sqrtf(g_ss[ch] / 16384.f + EPSV);
    else {
        int u = (ch - 16) / 3;
        sc = bngv[u] / sqrtf((g_ss[16 + 3 * u] + g_ss[17 + 3 * u] + g_ss[18 + 3 * u]) / 49152.f + EPSV);
    }
    g_scale[ch] = sc;
}

__global__ void scale_act_kernel(float* __restrict__ y, const float* __restrict__ bias) {
    int i = blockIdx.x * 256 + threadIdx.x;
    int ch = (i >> 12) & 63;
    float v = y[i] * g_scale[ch];
    if (ch < 16) v = fmaxf(v + bias[ch], 0.f);
    y[i] = v;
}

// ---------------- launch ----------------
extern "C" void kernel_launch(void* const* d_in, const int* in_sizes, int n_in,
                              void* d_out, int out_size) {
    const float* sv = (const float*)d_in[0];
    const float *wss, *wsv, *wst, *wvs, *wvv, *wvt;
    const float *bss, *bsv, *bst, *bvs, *bvv, *bvt;
    if (in_sizes[1] == 1029) {
        bss = (const float*)d_in[1];  wss = (const float*)d_in[2];
        bsv = (const float*)d_in[3];  wsv = (const float*)d_in[4];
        bst = (const float*)d_in[5];  wst = (const float*)d_in[6];
        bvs = (const float*)d_in[7];  wvs = (const float*)d_in[8];
        bvv = (const float*)d_in[9];  wvv = (const float*)d_in[10];
        bvt = (const float*)d_in[11]; wvt = (const float*)d_in[12];
    } else {
        wss = (const float*)d_in[1];  wsv = (const float*)d_in[2];  wst = (const float*)d_in[3];
        wvs = (const float*)d_in[4];  wvv = (const float*)d_in[5];  wvt = (const float*)d_in[6];
        bss = (const float*)d_in[7];  bsv = (const float*)d_in[8];  bst = (const float*)d_in[9];
        bvs = (const float*)d_in[10]; bvv = (const float*)d_in[11]; bvt = (const float*)d_in[12];
    }
    const float* bngs = (const float*)d_in[13];
    const float* bngv = (const float*)d_in[14];
    const float* bias = (const float*)d_in[15];
    float* out = (float*)d_out;

    const int SMEM_BYTES = (352 + 2 * 4536) * 4;   // 37,696 B
    cudaFuncSetAttribute(conv_kernel, cudaFuncAttributeMaxDynamicSharedMemorySize, SMEM_BYTES);

    int n1 = 104 * KTAPS * 64;
    build_w_kernel<<<(n1 + 255) / 256, 256>>>(0, 104, wss, wsv, wst, wvs, wvv, wvt,
                                              bss, bsv, bst, bvs, bvv, bvt);
    build_w_kernel<<<(n1 + 255) / 256, 256>>>(104, 208, wss, wsv, wst, wvs, wvv, wvt,
                                              bss, bsv, bst, bvs, bvv, bvt);
    long long nP = (long long)4 * IC * PCH;
    pad_kernel<<<(unsigned)((nP + 255) / 256), 256>>>(sv);
    conv_kernel<<<dim3(32, 4), 256, SMEM_BYTES>>>(out);
    sumsq_kernel<<<64, 256>>>(out);
    finalize_kernel<<<1, 64>>>(bngs, bngv);
    scale_act_kernel<<<4096, 256>>>(out, bias);
}

// round 17
// speedup vs baseline: 2.1445x; 2.1445x over previous
#include <cuda_runtime.h>
#include <cstdint>

#define OC 64
#define IC 208
#define EPSV 1e-5f
#define KTAPS 352
#define NK16 22
#define CHUNK_U4 256
#define BCH_U4 (NK16 * CHUNK_U4)      // 5632 uint4 per channel (90,112 B)
#define INW 4536                      // input tile floats (18,144 B, 16B-multiple)

// g_P: per-tile contiguous im2col blocks: [b][tile 32][c][4536]
__device__ float g_P[(size_t)4 * 32 * IC * INW];
__device__ uint4 g_W[(size_t)IC * BCH_U4];
__device__ float g_ss[OC];
__device__ float g_scale[OC];

// ---------------- helpers ----------------
static __device__ __forceinline__ uint32_t to_tf32(float x) {
    uint32_t r; asm("cvt.rn.tf32.f32 %0, %1;" : "=r"(r) : "f"(x));
    return r;
}
static __device__ __forceinline__ void mma_tf32(float* d, const uint32_t* a,
                                                uint32_t b0, uint32_t b1) {
    asm volatile("mma.sync.aligned.m16n8k8.row.col.f32.tf32.tf32.f32 "
        "{%0,%1,%2,%3}, {%4,%5,%6,%7}, {%8,%9}, {%0,%1,%2,%3};"
        : "+f"(d[0]), "+f"(d[1]), "+f"(d[2]), "+f"(d[3])
        : "r"(a[0]), "r"(a[1]), "r"(a[2]), "r"(a[3]), "r"(b0), "r"(b1));
}

#define MB_INIT(a, c) asm volatile("mbarrier.init.shared.b64 [%0], %1;" :: "r"(a), "r"(c) : "memory")
#define MB_EXPECT(a, bytes) \
    asm volatile("mbarrier.arrive.expect_tx.shared.b64 _, [%0], %1;" :: "r"(a), "r"(bytes) : "memory")
#define MB_WAIT(a, p) do {                                                      \
    asm volatile("{\n\t.reg .pred P1;\n\tW_%=:\n\t"                             \
        "mbarrier.try_wait.parity.acquire.cta.shared::cta.b64 P1, [%0], %1, 0x989680;\n\t" \
        "@P1 bra.uni D_%=;\n\tbra.uni W_%=;\n\tD_%=:\n\t}"                      \
        :: "r"(a), "r"((uint32_t)(p)) : "memory");                              \
} while (0)
#define BULK(dst, src, bytes, mbar)                                             \
    asm volatile("cp.async.bulk.shared::cluster.global.mbarrier::complete_tx::bytes " \
                 "[%0], [%1], %2, [%3];"                                        \
                 :: "r"(dst), "l"(src), "r"(bytes), "r"(mbar) : "memory")
#define FENCE_ASYNC() asm volatile("fence.proxy.async.shared::cta;" ::: "memory")

// ---------------- K1: build weights into tf32 mma B-fragment layout ----------------
__global__ void build_w_kernel(
    int c0, int c1,
    const float* __restrict__ wss, const float* __restrict__ wsv, const float* __restrict__ wst,
    const float* __restrict__ wvs, const float* __restrict__ wvv, const float* __restrict__ wvt,
    const float* __restrict__ bss, const float* __restrict__ bsv, const float* __restrict__ bst,
    const float* __restrict__ bvs, const float* __restrict__ bvv, const float* __restrict__ bvt) {
    int idx = blockIdx.x * blockDim.x + threadIdx.x;
    int n = (c1 - c0) * KTAPS * 64;
    if (idx >= n) return;
    int oc  = idx & 63;
    int tap = (idx >> 6) % KTAPS;
    int c   = c0 + idx / (KTAPS * 64);

    float val = 0.f;
    if (tap < 343) {
        int u, io, dout;
        if (oc < 16) { u = oc; io = 0; dout = 1; }
        else         { u = (oc - 16) / 3; io = (oc - 16) % 3; dout = 3; }
        int v, ji, din;
        if (c < 16)       { v = c;            ji = 0;            din = 1; }
        else if (c < 64)  { v = (c - 16) / 3; ji = (c - 16) % 3; din = 3; }
        else              { v = (c - 64) / 9; ji = (c - 64) % 9; din = 9; }
        const float* w; const float* bs; int nb;
        if (oc < 16) {
            if (c < 16)      { w = wss; bs = bss; nb = 3; }
            else if (c < 64) { w = wsv; bs = bsv; nb = 3; }
            else             { w = wst; bs = bst; nb = 9; }
        } else {
            if (c < 16)      { w = wvs; bs = bvs; nb = 3; }
            else if (c < 64) { w = wvv; bs = bvv; nb = 9; }
            else             { w = wvt; bs = bvt; nb = 21; }
        }
        for (int bb = 0; bb < nb; bb++)
            val = fmaf(w[(u * 16 + v) * nb + bb],
                       bs[((bb * dout + io) * din + ji) * 343 + tap], val);
    }
    int q = tap >> 4, kk = tap & 15;
    int j = oc >> 3;
    int lane = ((oc & 7) << 2) + (kk & 3);
    size_t u4 = ((size_t)c * NK16 + q) * CHUNK_U4 + j * 32 + lane;
    ((uint32_t*)&g_W[u4])[kk >> 2] = to_tf32(val);
}

// ---------------- K2: per-tile contiguous input blocks ----------------
// g_P[((b*32 + tile)*IC + c)*INW + i], i = dd*504 + dh*24 + ch (9 x 21 x 24)
__global__ void pad_kernel(const float* __restrict__ sv) {
    long long idx = (long long)blockIdx.x * 256 + threadIdx.x;
    if (idx >= (long long)4 * 32 * IC * INW) return;
    int i4 = (int)(idx % INW);
    long long r = idx / INW;
    int c    = (int)(r % IC);   r /= IC;
    int tile = (int)(r % 32);
    int b    = (int)(r / 32);

    int td = (tile >> 2) * 2, th = ((tile >> 1) & 1) * 8, tw = (tile & 1) * 8;
    int dd = i4 / 504; int rr = i4 - dd * 504;
    int dh = rr / 24;  int ch = rr - dh * 24;
    int id = 2 * td + dd - 3, ih = 2 * th + dh - 3, iw = 2 * tw + ch - 3;

    float val = 0.f;
    if ((unsigned)id < 32u && (unsigned)ih < 32u && (unsigned)iw < 32u) {
        int off = id * 1024 + ih * 32 + iw;
        const float* svb = sv + (size_t)b * 64 * 32768;
        if (c < 64) val = svb[(size_t)c * 32768 + off];
        else {
            int cc = c - 64, u = cc / 9, comp = cc % 9;
            val = svb[(size_t)(16 + u * 3 + comp / 3) * 32768 + off] *
                  svb[(size_t)(16 + u * 3 + comp % 3) * 32768 + off];
        }
    }
    g_P[idx] = val;
}

// ---------------- K3: mma.sync tf32, bulk-copy staging ----------------
// smem floats: [2..3] mbar0 (byte 8), [4..5] mbar1 (byte 16), [8..359] tapoff,
//              [360..] in 2x4536, [9432..] B 2x22528
extern __shared__ float smem[];

__global__ void __launch_bounds__(256, 1)
conv_kernel(float* __restrict__ out) {
    int*   tapoff = (int*)(smem + 8);
    float* s_in   = smem + 360;
    uint4* s_B    = (uint4*)(smem + 360 + 2 * INW);

    const int tid = threadIdx.x, lane = tid & 31, w = tid >> 5;
    const int tile = blockIdx.x, b = blockIdx.y;
    const int td = (tile >> 2) * 2, th = ((tile >> 1) & 1) * 8, tw = (tile & 1) * 8;

    const uint32_t sbase = (uint32_t)__cvta_generic_to_shared(smem);
    const uint32_t mb[2] = { sbase + 8, sbase + 16 };
    const uint32_t inb = sbase + 360 * 4;
    const uint32_t Bb  = sbase + (360 + 2 * INW) * 4;

    for (int t = tid; t < KTAPS; t += 256) {
        int kd = t / 49, r = t % 49, kh = r / 7, kw = r % 7;
        tapoff[t] = (t < 343) ? (kd * 504 + kh * 24 + kw) : 0;
    }
    if (tid == 0) { MB_INIT(mb[0], 1); MB_INIT(mb[1], 1); }
    __syncthreads();

    const float* gPt = g_P + ((size_t)(b * 32 + tile) * IC) * INW;

    // stage channel c into buffer c&1 (issued by tid 0)
    auto stage = [&](int c) {
        int buf = c & 1;
        FENCE_ASYNC();
        MB_EXPECT(mb[buf], 90112 + 18144);
        BULK(inb + (uint32_t)buf * INW * 4, gPt + (size_t)c * INW, 18144, mb[buf]);
        BULK(Bb + (uint32_t)buf * BCH_U4 * 16, g_W + (size_t)c * BCH_U4, 90112, mb[buf]);
    };

    const int c4 = lane & 3;
    const int m0 = w * 16 + (lane >> 2), m1 = m0 + 8;
    const int g0 = (m0 >> 6) * 1008 + ((m0 >> 3) & 7) * 48 + (m0 & 7) * 2;
    const int g1 = (m1 >> 6) * 1008 + ((m1 >> 3) & 7) * 48 + (m1 & 7) * 2;

    float acc[8][4];
#pragma unroll
    for (int j = 0; j < 8; j++)
#pragma unroll
        for (int k = 0; k < 4; k++) acc[j][k] = 0.f;

    if (tid == 0) { stage(0); stage(1); }

    for (int c = 0; c < IC; c++) {
        MB_WAIT(mb[c & 1], (c >> 1) & 1);

        const float* si = s_in + (c & 1) * INW;
        const uint4* Bc = s_B + (c & 1) * BCH_U4;

#pragma unroll 1
        for (int q = 0; q < NK16; q++) {
            const int* tq = tapoff + q * 16 + c4;
            int o0 = tq[0], o1 = tq[4], o2 = tq[8], o3 = tq[12];
            uint32_t a1[4], a2[4];
            a1[0] = to_tf32(si[g0 + o0]); a1[1] = to_tf32(si[g1 + o0]);
            a1[2] = to_tf32(si[g0 + o1]); a1[3] = to_tf32(si[g1 + o1]);
            a2[0] = to_tf32(si[g0 + o2]); a2[1] = to_tf32(si[g1 + o2]);
            a2[2] = to_tf32(si[g0 + o3]); a2[3] = to_tf32(si[g1 + o3]);

            const uint4* Bq = Bc + q * CHUNK_U4 + lane;
#pragma unroll
            for (int j = 0; j < 8; j++) {
                uint4 bb = Bq[j * 32];
                mma_tf32(acc[j], a1, bb.x, bb.y);
                mma_tf32(acc[j], a2, bb.z, bb.w);
            }
        }

        __syncthreads();                       // all warps done with buffer c&1
        if (c + 2 < IC && tid == 0) stage(c + 2);
    }

    // epilogue: D frag (row lane/4 [+8], col j*8 + 2*c4 [+1])
    const int od0 = td + (m0 >> 6), oh0 = th + ((m0 >> 3) & 7), ow0 = tw + (m0 & 7);
    const int od1 = td + (m1 >> 6), oh1 = th + ((m1 >> 3) & 7), ow1 = tw + (m1 & 7);
    float* ob = out + (size_t)b * OC * 4096;
    const int v0 = od0 * 256 + oh0 * 16 + ow0;
    const int v1 = od1 * 256 + oh1 * 16 + ow1;
#pragma unroll
    for (int j = 0; j < 8; j++) {
        int oc0 = j * 8 + 2 * c4;
        ob[(size_t)oc0 * 4096 + v0]       = acc[j][0];
        ob[(size_t)(oc0 + 1) * 4096 + v0] = acc[j][1];
        ob[(size_t)oc0 * 4096 + v1]       = acc[j][2];
        ob[(size_t)(oc0 + 1) * 4096 + v1] = acc[j][3];
    }
}

// ---------------- epilogue kernels ----------------
__global__ void sumsq_kernel(const float* __restrict__ y) {
    __shared__ float red[256];
    const int ch = blockIdx.x, tid = threadIdx.x;
    float s = 0.f;
    for (int i = tid; i < 4 * 4096; i += 256) {
        int b = i >> 12, sp = i & 4095;
        float v = y[((size_t)b * OC + ch) * 4096 + sp];
        s = fmaf(v, v, s);
    }
    red[tid] = s;
    __syncthreads();
    for (int o = 128; o > 0; o >>= 1) {
        if (tid < o) red[tid] += red[tid + o];
        __syncthreads();
    }
    if (tid == 0) g_ss[ch] = red[0];
}

__global__ void finalize_kernel(const float* __restrict__ bngs, const float* __restrict__ bngv) {
    int ch = threadIdx.x;
    float sc;
    if (ch < 16) sc = bngs[ch] / sqrtf(g_ss[ch] / 16384.f + EPSV);
    else {
        int u = (ch - 16) / 3;
        sc = bngv[u] / sqrtf((g_ss[16 + 3 * u] + g_ss[17 + 3 * u] + g_ss[18 + 3 * u]) / 49152.f + EPSV);
    }
    g_scale[ch] = sc;
}

__global__ void scale_act_kernel(float* __restrict__ y, const float* __restrict__ bias) {
    int i = blockIdx.x * 256 + threadIdx.x;
    int ch = (i >> 12) & 63;
    float v = y[i] * g_scale[ch];
    if (ch < 16) v = fmaxf(v + bias[ch], 0.f);
    y[i] = v;
}

// ---------------- launch ----------------
extern "C" void kernel_launch(void* const* d_in, const int* in_sizes, int n_in,
                              void* d_out, int out_size) {
    const float* sv = (const float*)d_in[0];
    const float *wss, *wsv, *wst, *wvs, *wvv, *wvt;
    const float *bss, *bsv, *bst, *bvs, *bvv, *bvt;
    if (in_sizes[1] == 1029) {
        bss = (const float*)d_in[1];  wss = (const float*)d_in[2];
        bsv = (const float*)d_in[3];  wsv = (const float*)d_in[4];
        bst = (const float*)d_in[5];  wst = (const float*)d_in[6];
        bvs = (const float*)d_in[7];  wvs = (const float*)d_in[8];
        bvv = (const float*)d_in[9];  wvv = (const float*)d_in[10];
        bvt = (const float*)d_in[11]; wvt = (const float*)d_in[12];
    } else {
        wss = (const float*)d_in[1];  wsv = (const float*)d_in[2];  wst = (const float*)d_in[3];
        wvs = (const float*)d_in[4];  wvv = (const float*)d_in[5];  wvt = (const float*)d_in[6];
        bss = (const float*)d_in[7];  bsv = (const float*)d_in[8];  bst = (const float*)d_in[9];
        bvs = (const float*)d_in[10]; bvv = (const float*)d_in[11]; bvt = (const float*)d_in[12];
    }
    const float* bngs = (const float*)d_in[13];
    const float* bngv = (const float*)d_in[14];
    const float* bias = (const float*)d_in[15];
    float* out = (float*)d_out;

    const int SMEM_BYTES = (360 + 2 * INW + 2 * BCH_U4 * 4) * 4;   // 217,952 B
    cudaFuncSetAttribute(conv_kernel, cudaFuncAttributeMaxDynamicSharedMemorySize, SMEM_BYTES);

    int n1 = 104 * KTAPS * 64;
    build_w_kernel<<<(n1 + 255) / 256, 256>>>(0, 104, wss, wsv, wst, wvs, wvv, wvt,
                                              bss, bsv, bst, bvs, bvv, bvt);
    build_w_kernel<<<(n1 + 255) / 256, 256>>>(104, 208, wss, wsv, wst, wvs, wvv, wvt,
                                              bss, bsv, bst, bvs, bvv, bvt);
    long long nP = (long long)4 * 32 * IC * INW;
    pad_kernel<<<(unsigned)((nP + 255) / 256), 256>>>(sv);
    conv_kernel<<<dim3(32, 4), 256, SMEM_BYTES>>>(out);
    sumsq_kernel<<<64, 256>>>(out);
    finalize_kernel<<<1, 64>>>(bngs, bngv);
    scale_act_kernel<<<4096, 256>>>(out, bias);
}